// round 11
// baseline (speedup 1.0000x reference)
#include <cuda_runtime.h>
#include <cuda_bf16.h>
#include <cuda_fp16.h>
#include <math.h>
#include <stdint.h>

// Problem constants
#define B_  2
#define S_  2048
#define E_  1024
#define H_  16
#define HD_ 64
#define M_TOK (B_ * S_)          // 4096
#define QKV_N (3 * E_)           // 3072

// ---------------------------------------------------------------------------
// Scratch (no allocation allowed -> __device__ globals)
// ---------------------------------------------------------------------------
__device__ float g_O1[B_ * H_ * S_ * HD_];
__device__ float g_O2[B_ * H_ * S_ * HD_];
__device__ float g_lam;
__device__ __half g_x16[M_TOK * E_];              // x fp16
__device__ __half g_qkv16[M_TOK * QKV_N];         // qkv fp16
__device__ __half g_X216[M_TOK * E_];             // scrambled pre-wo fp16
__device__ __half g_wqkvT16[QKV_N * E_];          // [3072,1024] K-major fp16
__device__ __half g_woT16[E_ * E_];               // [1024,1024] K-major fp16

// ---------------------------------------------------------------------------
// Helpers
// ---------------------------------------------------------------------------
__device__ __forceinline__ uint32_t smem_to_u32(const void* p) {
    uint32_t a;
    asm("{ .reg .u64 tmp; cvta.to.shared.u64 tmp, %1; cvt.u32.u64 %0, tmp; }"
        : "=r"(a) : "l"(p));
    return a;
}
#define CP16(daddr, gptr) \
    asm volatile("cp.async.cg.shared.global [%0], [%1], 16;" \
                 :: "r"(daddr), "l"(gptr))
#define CP_COMMIT() asm volatile("cp.async.commit_group;")
#define LDSM4(r, addr) \
    asm volatile("ldmatrix.sync.aligned.m8n8.x4.shared.b16 {%0,%1,%2,%3}, [%4];" \
                 : "=r"((r)[0]), "=r"((r)[1]), "=r"((r)[2]), "=r"((r)[3]) \
                 : "r"(addr))
#define LDSM4T(r, addr) \
    asm volatile("ldmatrix.sync.aligned.m8n8.x4.trans.shared.b16 {%0,%1,%2,%3}, [%4];" \
                 : "=r"((r)[0]), "=r"((r)[1]), "=r"((r)[2]), "=r"((r)[3]) \
                 : "r"(addr))
#define MMAF16(d, a, b0_, b1_) \
    asm volatile("mma.sync.aligned.m16n8k16.row.col.f32.f16.f16.f32 " \
                 "{%0,%1,%2,%3}, {%4,%5,%6,%7}, {%8,%9}, {%0,%1,%2,%3};" \
                 : "+f"((d)[0]), "+f"((d)[1]), "+f"((d)[2]), "+f"((d)[3]) \
                 : "r"((a)[0]), "r"((a)[1]), "r"((a)[2]), "r"((a)[3]), \
                   "r"(b0_), "r"(b1_))
#define SMEM_SWIZZLE_128B(byte_offset) \
    ((byte_offset) ^ (((byte_offset) >> 3) & 0x70))

// ---------------------------------------------------------------------------
// Weight transpose + fp16 convert:  in [K,N] fp32  ->  out [N,K] fp16
// ---------------------------------------------------------------------------
__global__ __launch_bounds__(256) void transpose_f16(
    const float* __restrict__ in, __half* __restrict__ o16, int K, int N)
{
    __shared__ float t[32][33];
    const int tx = threadIdx.x & 31, ty = threadIdx.x >> 5;
    const int n0 = blockIdx.x * 32, k0 = blockIdx.y * 32;
#pragma unroll
    for (int j = 0; j < 32; j += 8)
        t[ty + j][tx] = in[(size_t)(k0 + ty + j) * N + n0 + tx];
    __syncthreads();
#pragma unroll
    for (int j = 0; j < 32; j += 8)
        o16[(size_t)(n0 + ty + j) * K + k0 + tx] = __float2half(t[tx][ty + j]);
}

// ---------------------------------------------------------------------------
// Elementwise fp32 -> fp16 (for x)
// ---------------------------------------------------------------------------
__global__ __launch_bounds__(256) void tof16_kernel(
    const float* __restrict__ in, __half* __restrict__ o16)
{
    int i = (blockIdx.x * 256 + threadIdx.x) * 4;
    float4 v = *(const float4*)(in + i);
    __half2* p = (__half2*)(o16 + i);
    p[0] = __floats2half2_rn(v.x, v.y);
    p[1] = __floats2half2_rn(v.z, v.w);
}

// ---------------------------------------------------------------------------
// Tensor-core GEMM, single-pass fp16 (unchanged from R10)
// ---------------------------------------------------------------------------
#define PITCH 72
#define BUFB  (128 * PITCH * 2)       // 18432 B
#define STAGEB (2 * BUFB)             // 36864 B
#define GEMM_SMEM (2 * STAGEB)        // 73728 B

template <int OUTF>
__global__ void __launch_bounds__(256, 2) mma_gemm(
    const __half* __restrict__ A, const __half* __restrict__ Bm,
    float* __restrict__ C, __half* __restrict__ Cf, int M, int N, int K)
{
    extern __shared__ __align__(16) uint8_t smem[];
    const uint32_t sbase = smem_to_u32(smem);
    const int tid = threadIdx.x, lane = tid & 31, wid = tid >> 5;
    const int wr = wid & 3, wc = wid >> 2;
    const int bm = blockIdx.y * 128, bn = blockIdx.x * 128;
    const int NK = K / 64;

    float acc[2][8][4];
#pragma unroll
    for (int i = 0; i < 2; i++)
#pragma unroll
        for (int j = 0; j < 8; j++)
#pragma unroll
            for (int r = 0; r < 4; r++) acc[i][j][r] = 0.f;

#define ISSUE(kt, stg) do {                                                    \
        uint32_t sb_ = sbase + (stg) * STAGEB;                                 \
        _Pragma("unroll")                                                      \
        for (int hf = 0; hf < 4; hf++) {                                       \
            int c = tid + hf * 256;                                            \
            int row = c >> 3, colc = (c & 7) * 8;                              \
            uint32_t doff = (uint32_t)(row * (PITCH * 2) + colc * 2);          \
            CP16(sb_ + doff, A + (size_t)(bm + row) * K + (kt) * 64 + colc);   \
            CP16(sb_ + BUFB + doff,                                            \
                 Bm + (size_t)(bn + row) * K + (kt) * 64 + colc);              \
        }                                                                      \
        CP_COMMIT();                                                           \
    } while (0)

    ISSUE(0, 0);

    for (int kt = 0; kt < NK; kt++) {
        const int cur = kt & 1;
        if (kt + 1 < NK) {
            ISSUE(kt + 1, (kt + 1) & 1);
            asm volatile("cp.async.wait_group 1;");
        } else {
            asm volatile("cp.async.wait_group 0;");
        }
        __syncthreads();

        const uint32_t sA = sbase + cur * STAGEB;
        const uint32_t sB = sA + BUFB;

#pragma unroll
        for (int ks = 0; ks < 4; ks++) {
            uint32_t ah[2][4];
#pragma unroll
            for (int i = 0; i < 2; i++) {
                uint32_t ra = (uint32_t)((wr * 32 + i * 16 + (lane & 15)) * (PITCH * 2)
                              + (ks * 16 + ((lane >> 4) << 3)) * 2);
                LDSM4(ah[i], sA + ra);
            }
#pragma unroll
            for (int jp = 0; jp < 4; jp++) {
                uint32_t rowb = (uint32_t)(wc * 64 + jp * 16 + ((lane >> 4) << 3) + (lane & 7));
                uint32_t colb = (uint32_t)(ks * 16 + (((lane >> 3) & 1) << 3));
                uint32_t rb = rowb * (PITCH * 2) + colb * 2;
                uint32_t bh4[4];
                LDSM4(bh4, sB + rb);
                MMAF16(acc[0][jp * 2],     ah[0], bh4[0], bh4[1]);
                MMAF16(acc[1][jp * 2],     ah[1], bh4[0], bh4[1]);
                MMAF16(acc[0][jp * 2 + 1], ah[0], bh4[2], bh4[3]);
                MMAF16(acc[1][jp * 2 + 1], ah[1], bh4[2], bh4[3]);
            }
        }
        __syncthreads();
    }

#pragma unroll
    for (int i = 0; i < 2; i++) {
        int mrow = bm + wr * 32 + i * 16 + (lane >> 2);
#pragma unroll
        for (int j = 0; j < 8; j++) {
            int ncol = bn + wc * 64 + j * 8 + (lane & 3) * 2;
            if (OUTF == 0) {
                *(float2*)(C + (size_t)mrow * N + ncol) =
                    make_float2(acc[i][j][0], acc[i][j][1]);
                *(float2*)(C + (size_t)(mrow + 8) * N + ncol) =
                    make_float2(acc[i][j][2], acc[i][j][3]);
            } else {
                *(__half2*)(Cf + (size_t)mrow * N + ncol) =
                    __floats2half2_rn(acc[i][j][0], acc[i][j][1]);
                *(__half2*)(Cf + (size_t)(mrow + 8) * N + ncol) =
                    __floats2half2_rn(acc[i][j][2], acc[i][j][3]);
            }
        }
    }
#undef ISSUE
}

// ---------------------------------------------------------------------------
// Lambda scalar
// ---------------------------------------------------------------------------
__global__ void lambda_kernel(const float* __restrict__ lq1, const float* __restrict__ lq2,
                              const float* __restrict__ lk1, const float* __restrict__ lk2)
{
    if (threadIdx.x == 0) {
        float d1 = 0.f, d2 = 0.f;
        for (int i = 0; i < HD_; i++) { d1 += lq1[i] * lk1[i]; d2 += lq2[i] * lk2[i]; }
        g_lam = expf(d1) - expf(d2) + 0.8f;
    }
}

// ---------------------------------------------------------------------------
// Tensor-core flash attention, fp16.
// V loaded DIRECTLY from row-major qkv ([key][d] rows, pitch 144B) and
// consumed via ldmatrix.trans — no V^T pre-transpose kernel.
// Softmax exponentials via h2exp2 (fp16x2 MUFU, half the instruction count);
// result is already the packed fp16 P fragment.
// smem: Q[0,10240) | K stages 10240+stg*10240 (sub +5120)
//       | V stages 30720+stg*18432 (sub +9216)
// ---------------------------------------------------------------------------
#define SQ_OFF 0
#define SK_OFF 10240
#define SV_OFF 30720
#define VPITCHB 144
#define ATT_SMEM 67584
#define NT_ (S_ / 128)

__global__ void __launch_bounds__(256, 2) attn_mma(
    const __half* __restrict__ q16, float* __restrict__ O1, float* __restrict__ O2)
{
    extern __shared__ __align__(16) uint8_t smem[];
    const uint32_t sbase = smem_to_u32(smem);
    const int tid = threadIdx.x, lane = tid & 31, wr = tid >> 5;
    const int bh = blockIdx.y, b = bh >> 4, h = bh & 15;
    const int half = blockIdx.z, d0 = half << 5;
    const int q0 = blockIdx.x * 128;

    const size_t qkoff = (size_t)b * S_ * QKV_N + h * HD_ + d0;
    const size_t voff  = (size_t)b * S_ * QKV_N + 2 * E_ + h * HD_;

#pragma unroll
    for (int rep = 0; rep < 2; rep++) {
        int idx = tid + rep * 256;
        int row = idx >> 2, ch = idx & 3;
        size_t g = qkoff + (size_t)(q0 + row) * QKV_N + ch * 8;
        CP16(sbase + SQ_OFF + (uint32_t)(row * 80 + ch * 16), q16 + g);
    }

    // 128-key tile = two 64-key halves, one commit
    auto issue_tile = [&](int t, int stg) {
        uint32_t kb = sbase + SK_OFF + stg * 10240;
        uint32_t vb = sbase + SV_OFF + stg * 18432;
#pragma unroll
        for (int sub = 0; sub < 2; sub++) {
            {   // K: 64 rows x 64B (half head)
                int row = tid >> 2, ch = tid & 3;
                size_t g = qkoff + (size_t)E_
                         + (size_t)(t * 128 + sub * 64 + row) * QKV_N + ch * 8;
                CP16(kb + sub * 5120 + (uint32_t)(row * 80 + ch * 16), q16 + g);
            }
            // V: 64 rows x 128B (full head), row-major [key][d], pitch 144B
#pragma unroll
            for (int rep = 0; rep < 2; rep++) {
                int idx = tid + rep * 256;
                int row = idx >> 3, ch = idx & 7;
                size_t g = voff + (size_t)(t * 128 + sub * 64 + row) * QKV_N + ch * 8;
                CP16(vb + sub * 9216 + (uint32_t)(row * VPITCHB + ch * 16), q16 + g);
            }
        }
        CP_COMMIT();
    };

    issue_tile(0, 0);
    issue_tile(1, 1);

    float o[8][4];
#pragma unroll
    for (int j = 0; j < 8; j++)
#pragma unroll
        for (int r = 0; r < 4; r++) o[j][r] = 0.f;
    float m0 = -1e30f, m1 = -1e30f, l0 = 0.f, l1 = 0.f;
    uint32_t ah[2][4];

    const float CSC = 0.125f * 1.4426950408889634f;

    for (int t = 0; t < NT_; t++) {
        if (t < NT_ - 1) asm volatile("cp.async.wait_group 1;");
        else             asm volatile("cp.async.wait_group 0;");
        __syncthreads();

        if (t == 0) {
#pragma unroll
            for (int ks = 0; ks < 2; ks++) {
                uint32_t ra = sbase + SQ_OFF + (uint32_t)((wr * 16 + (lane & 15)) * 80
                              + (ks * 16 + ((lane >> 4) << 3)) * 2);
                LDSM4(ah[ks], ra);
            }
        }

#pragma unroll
        for (int sub = 0; sub < 2; sub++) {
            // ---- S = Q K^T (fp16) ----
            float s[8][4];
#pragma unroll
            for (int j = 0; j < 8; j++)
#pragma unroll
                for (int r = 0; r < 4; r++) s[j][r] = 0.f;

            const uint32_t kb = sbase + SK_OFF + (t & 1) * 10240 + sub * 5120;
#pragma unroll
            for (int ks = 0; ks < 2; ks++) {
#pragma unroll
                for (int jp = 0; jp < 4; jp++) {
                    uint32_t ra = kb + (uint32_t)(
                        (jp * 16 + ((lane >> 4) << 3) + (lane & 7)) * 80
                        + (ks * 16 + (((lane >> 3) & 1) << 3)) * 2);
                    uint32_t kh4[4];
                    LDSM4(kh4, ra);
                    MMAF16(s[jp * 2],     ah[ks], kh4[0], kh4[1]);
                    MMAF16(s[jp * 2 + 1], ah[ks], kh4[2], kh4[3]);
                }
            }

            // ---- online softmax ----
            float mx0 = -1e30f, mx1 = -1e30f;
#pragma unroll
            for (int j = 0; j < 8; j++) {
                mx0 = fmaxf(mx0, fmaxf(s[j][0], s[j][1]));
                mx1 = fmaxf(mx1, fmaxf(s[j][2], s[j][3]));
            }
            mx0 = fmaxf(mx0, __shfl_xor_sync(0xffffffffu, mx0, 1));
            mx0 = fmaxf(mx0, __shfl_xor_sync(0xffffffffu, mx0, 2));
            mx1 = fmaxf(mx1, __shfl_xor_sync(0xffffffffu, mx1, 1));
            mx1 = fmaxf(mx1, __shfl_xor_sync(0xffffffffu, mx1, 2));
            const float nm0 = fmaxf(m0, mx0 * CSC), nm1 = fmaxf(m1, mx1 * CSC);
            const float sc0 = exp2f(m0 - nm0), sc1 = exp2f(m1 - nm1);
            m0 = nm0; m1 = nm1;
            l0 *= sc0; l1 *= sc1;
#pragma unroll
            for (int j = 0; j < 8; j++) {
                o[j][0] *= sc0; o[j][1] *= sc0; o[j][2] *= sc1; o[j][3] *= sc1;
            }

            uint32_t pah[4][4];
#pragma unroll
            for (int kp = 0; kp < 4; kp++) {
#pragma unroll
                for (int fi = 0; fi < 2; fi++) {
                    const int jf = kp * 2 + fi;
                    // args in fp16x2, exp via MUFU f16x2 (half the instructions);
                    // output IS the fp16 P fragment.
                    __half2 a01 = __floats2half2_rn(fmaf(s[jf][0], CSC, -nm0),
                                                    fmaf(s[jf][1], CSC, -nm0));
                    __half2 a23 = __floats2half2_rn(fmaf(s[jf][2], CSC, -nm1),
                                                    fmaf(s[jf][3], CSC, -nm1));
                    __half2 p01 = h2exp2(a01);
                    __half2 p23 = h2exp2(a23);
                    float2 f01 = __half22float2(p01);
                    float2 f23 = __half22float2(p23);
                    l0 += f01.x + f01.y;
                    l1 += f23.x + f23.y;
                    pah[kp][fi * 2]     = *(uint32_t*)&p01;
                    pah[kp][fi * 2 + 1] = *(uint32_t*)&p23;
                }
            }

            // ---- O += P V (fp16), V via ldmatrix.trans from [key][d] rows ----
            const uint32_t vb = sbase + SV_OFF + (t & 1) * 18432 + sub * 9216;
#pragma unroll
            for (int kp = 0; kp < 4; kp++) {
#pragma unroll
                for (int jn = 0; jn < 4; jn++) {
                    uint32_t va = vb + (uint32_t)(
                        (kp * 16 + (((lane >> 3) & 1) << 3) + (lane & 7)) * VPITCHB
                        + (jn * 16 + ((lane >> 4) << 3)) * 2);
                    uint32_t vh4[4];
                    LDSM4T(vh4, va);
                    MMAF16(o[jn * 2],     pah[kp], vh4[0], vh4[1]);
                    MMAF16(o[jn * 2 + 1], pah[kp], vh4[2], vh4[3]);
                }
            }
        }
        __syncthreads();
        if (t + 2 < NT_) issue_tile(t + 2, t & 1);
    }

    l0 += __shfl_xor_sync(0xffffffffu, l0, 1);
    l0 += __shfl_xor_sync(0xffffffffu, l0, 2);
    l1 += __shfl_xor_sync(0xffffffffu, l1, 1);
    l1 += __shfl_xor_sync(0xffffffffu, l1, 2);
    const float inv0 = 1.f / l0, inv1 = 1.f / l1;
    const int g = lane >> 2, tq = lane & 3;
    float* Op = (half ? O2 : O1) + ((size_t)bh * S_ + q0 + wr * 16) * HD_;
#pragma unroll
    for (int jf = 0; jf < 8; jf++) {
        int col = jf * 8 + tq * 2;
        *(float2*)(Op + (size_t)g * HD_ + col) =
            make_float2(o[jf][0] * inv0, o[jf][1] * inv0);
        *(float2*)(Op + (size_t)(g + 8) * HD_ + col) =
            make_float2(o[jf][2] * inv1, o[jf][3] * inv1);
    }
}

// ---------------------------------------------------------------------------
// Combine + RMSNorm + scrambled reshape -> fp16 (SMEM-transposed)
// ---------------------------------------------------------------------------
__global__ __launch_bounds__(256) void combine_kernel(
    const float* __restrict__ O1, const float* __restrict__ O2,
    const float* __restrict__ normw, __half* __restrict__ X2)
{
    __shared__ ushort smh[64][40];

    const int bh = blockIdx.y, b = bh >> 4, h = bh & 15;
    const int s0 = blockIdx.x * 32;
    const int tid = threadIdx.x;
    const int sr = tid >> 3;
    const int dp = (tid & 7) * 8;

    const float lam = g_lam;
    const size_t rbase = ((size_t)bh * S_ + s0 + sr) * HD_ + dp;

    float a[8];
    float ss = 0.f;
#pragma unroll
    for (int c = 0; c < 2; c++) {
        float4 v1 = *(const float4*)(O1 + rbase + c * 4);
        float4 v2 = *(const float4*)(O2 + rbase + c * 4);
        a[c * 4 + 0] = v1.x - lam * v2.x;
        a[c * 4 + 1] = v1.y - lam * v2.y;
        a[c * 4 + 2] = v1.z - lam * v2.z;
        a[c * 4 + 3] = v1.w - lam * v2.w;
#pragma unroll
        for (int j = 0; j < 4; j++) ss += a[c * 4 + j] * a[c * 4 + j];
    }
    ss += __shfl_xor_sync(0xffffffffu, ss, 1);
    ss += __shfl_xor_sync(0xffffffffu, ss, 2);
    ss += __shfl_xor_sync(0xffffffffu, ss, 4);
    const float inv = rsqrtf(ss * (1.f / 64.f) + 1e-6f) * (1.0f - 0.8f);

#pragma unroll
    for (int j = 0; j < 8; j++) {
        float v = a[j] * inv * normw[h * HD_ + dp + j];
        smh[dp + j][sr] = __half_as_ushort(__float2half(v));
    }
    __syncthreads();

    const int dr = tid >> 2, chunk = tid & 3;
    const int shi = s0 >> 10, slo0 = s0 & 1023;
    const size_t obase = (size_t)b * S_ * E_ + (size_t)(dr * 32 + h * 2 + shi) * E_
                       + slo0 + chunk * 8;
    *(uint4*)(X2 + obase) = *(const uint4*)(&smh[dr][chunk * 8]);
}

// ---------------------------------------------------------------------------
// Launch
// ---------------------------------------------------------------------------
extern "C" void kernel_launch(void* const* d_in, const int* in_sizes, int n_in,
                              void* d_out, int out_size)
{
    const float* x     = (const float*)d_in[0];
    const float* w_qkv = (const float*)d_in[1];
    const float* wo    = (const float*)d_in[2];
    const float* lq1   = (const float*)d_in[3];
    const float* lq2   = (const float*)d_in[4];
    const float* lk1   = (const float*)d_in[5];
    const float* lk2   = (const float*)d_in[6];
    const float* normw = (const float*)d_in[7];
    float* out = (float*)d_out;

    float *p_O1, *p_O2;
    cudaGetSymbolAddress((void**)&p_O1, g_O1);
    cudaGetSymbolAddress((void**)&p_O2, g_O2);
    __half *p_x16, *p_q16, *p_X216, *p_wq16, *p_wo16;
    cudaGetSymbolAddress((void**)&p_x16, g_x16);
    cudaGetSymbolAddress((void**)&p_q16, g_qkv16);
    cudaGetSymbolAddress((void**)&p_X216, g_X216);
    cudaGetSymbolAddress((void**)&p_wq16, g_wqkvT16);
    cudaGetSymbolAddress((void**)&p_wo16, g_woT16);

    cudaFuncSetAttribute(mma_gemm<0>, cudaFuncAttributeMaxDynamicSharedMemorySize, GEMM_SMEM);
    cudaFuncSetAttribute(mma_gemm<1>, cudaFuncAttributeMaxDynamicSharedMemorySize, GEMM_SMEM);
    cudaFuncSetAttribute(attn_mma, cudaFuncAttributeMaxDynamicSharedMemorySize, ATT_SMEM);

    // 0) fp16 conversions
    tof16_kernel<<<(M_TOK * E_) / (256 * 4), 256>>>(x, p_x16);
    transpose_f16<<<dim3(QKV_N / 32, E_ / 32), 256>>>(w_qkv, p_wq16, E_, QKV_N);
    transpose_f16<<<dim3(E_ / 32, E_ / 32), 256>>>(wo, p_wo16, E_, E_);

    // 1) QKV projection (fp16 single-pass) -> fp16
    mma_gemm<1><<<dim3(QKV_N / 128, M_TOK / 128), 256, GEMM_SMEM>>>(
        p_x16, p_wq16, nullptr, p_q16, M_TOK, QKV_N, E_);

    // 2) lambda
    lambda_kernel<<<1, 32>>>(lq1, lq2, lk1, lk2);

    // 3) fp16 tensor-core attention, both halves (V direct from qkv)
    attn_mma<<<dim3(S_ / 128, B_ * H_, 2), 256, ATT_SMEM>>>(p_q16, p_O1, p_O2);

    // 4) combine + RMSNorm + scrambled reshape -> fp16
    combine_kernel<<<dim3(S_ / 32, B_ * H_), 256>>>(p_O1, p_O2, normw, p_X216);

    // 5) output projection (fp16 single-pass) -> fp32 d_out
    mma_gemm<0><<<dim3(E_ / 128, M_TOK / 128), 256, GEMM_SMEM>>>(
        p_X216, p_wo16, out, nullptr, M_TOK, E_, E_);
}

// round 13
// speedup vs baseline: 1.0114x; 1.0114x over previous
#include <cuda_runtime.h>
#include <cuda_bf16.h>
#include <cuda_fp16.h>
#include <math.h>
#include <stdint.h>

// Problem constants
#define B_  2
#define S_  2048
#define E_  1024
#define H_  16
#define HD_ 64
#define M_TOK (B_ * S_)          // 4096
#define QKV_N (3 * E_)           // 3072

// ---------------------------------------------------------------------------
// Scratch (no allocation allowed -> __device__ globals)
// ---------------------------------------------------------------------------
__device__ float g_O1[B_ * H_ * S_ * HD_];
__device__ float g_O2[B_ * H_ * S_ * HD_];
__device__ float g_lam;
__device__ __half g_x16[M_TOK * E_];              // x fp16
__device__ __half g_qkv16[M_TOK * QKV_N];         // qkv fp16
__device__ __half g_vt16[B_ * H_ * HD_ * S_];     // V^T [b,h,d,s] fp16
__device__ __half g_X216[M_TOK * E_];             // scrambled pre-wo fp16
__device__ __half g_wqkvT16[QKV_N * E_];          // [3072,1024] K-major fp16
__device__ __half g_woT16[E_ * E_];               // [1024,1024] K-major fp16

// ---------------------------------------------------------------------------
// Helpers
// ---------------------------------------------------------------------------
__device__ __forceinline__ uint32_t smem_to_u32(const void* p) {
    uint32_t a;
    asm("{ .reg .u64 tmp; cvta.to.shared.u64 tmp, %1; cvt.u32.u64 %0, tmp; }"
        : "=r"(a) : "l"(p));
    return a;
}
#define CP16(daddr, gptr) \
    asm volatile("cp.async.cg.shared.global [%0], [%1], 16;" \
                 :: "r"(daddr), "l"(gptr))
#define CP_COMMIT() asm volatile("cp.async.commit_group;")
#define LDSM4(r, addr) \
    asm volatile("ldmatrix.sync.aligned.m8n8.x4.shared.b16 {%0,%1,%2,%3}, [%4];" \
                 : "=r"((r)[0]), "=r"((r)[1]), "=r"((r)[2]), "=r"((r)[3]) \
                 : "r"(addr))
#define MMAF16(d, a, b0_, b1_) \
    asm volatile("mma.sync.aligned.m16n8k16.row.col.f32.f16.f16.f32 " \
                 "{%0,%1,%2,%3}, {%4,%5,%6,%7}, {%8,%9}, {%0,%1,%2,%3};" \
                 : "+f"((d)[0]), "+f"((d)[1]), "+f"((d)[2]), "+f"((d)[3]) \
                 : "r"((a)[0]), "r"((a)[1]), "r"((a)[2]), "r"((a)[3]), \
                   "r"(b0_), "r"(b1_))
// pack two fp32 -> f16x2 (lo = first value arg, hi = second)
#define PACKH(r, lo_, hi_) \
    asm("cvt.rn.f16x2.f32 %0, %1, %2;" : "=r"(r) : "f"(hi_), "f"(lo_))
#define SMEM_SWIZZLE_128B(byte_offset) \
    ((byte_offset) ^ (((byte_offset) >> 3) & 0x70))

// ---------------------------------------------------------------------------
// Weight transpose + fp16 convert:  in [K,N] fp32  ->  out [N,K] fp16
// ---------------------------------------------------------------------------
__global__ __launch_bounds__(256) void transpose_f16(
    const float* __restrict__ in, __half* __restrict__ o16, int K, int N)
{
    __shared__ float t[32][33];
    const int tx = threadIdx.x & 31, ty = threadIdx.x >> 5;
    const int n0 = blockIdx.x * 32, k0 = blockIdx.y * 32;
#pragma unroll
    for (int j = 0; j < 32; j += 8)
        t[ty + j][tx] = in[(size_t)(k0 + ty + j) * N + n0 + tx];
    __syncthreads();
#pragma unroll
    for (int j = 0; j < 32; j += 8)
        o16[(size_t)(n0 + ty + j) * K + k0 + tx] = __float2half(t[tx][ty + j]);
}

// ---------------------------------------------------------------------------
// Elementwise fp32 -> fp16 (for x)
// ---------------------------------------------------------------------------
__global__ __launch_bounds__(256) void tof16_kernel(
    const float* __restrict__ in, __half* __restrict__ o16)
{
    int i = (blockIdx.x * 256 + threadIdx.x) * 4;
    float4 v = *(const float4*)(in + i);
    __half2* p = (__half2*)(o16 + i);
    p[0] = __floats2half2_rn(v.x, v.y);
    p[1] = __floats2half2_rn(v.z, v.w);
}

// ---------------------------------------------------------------------------
// V transpose (fp16): qkv v-part [b,s,h,d] -> [b,h,d,s]
// ---------------------------------------------------------------------------
__global__ __launch_bounds__(256) void vtrans_kernel(
    const __half* __restrict__ q16, __half* __restrict__ vt16)
{
    __shared__ __half t[32][33];
    const int bh = blockIdx.z, b = bh >> 4, h = bh & 15;
    const int s0 = blockIdx.x * 32, d0 = blockIdx.y * 32;
    const int tx = threadIdx.x & 31, ty = threadIdx.x >> 5;
#pragma unroll
    for (int j = 0; j < 32; j += 8) {
        size_t ga = (size_t)(b * S_ + s0 + ty + j) * QKV_N + 2 * E_ + h * HD_ + d0 + tx;
        t[ty + j][tx] = q16[ga];
    }
    __syncthreads();
#pragma unroll
    for (int j = 0; j < 32; j += 8) {
        size_t go = (size_t)(bh * HD_ + d0 + ty + j) * S_ + s0 + tx;
        vt16[go] = t[tx][ty + j];
    }
}

// ---------------------------------------------------------------------------
// Tensor-core GEMM, single-pass fp16: C = A @ B^T, fp32 accumulate.
// A: [M,K] fp16 row-major; B: [N,K] fp16 K-major.
// 128x128 tile, BK=64 per stage, 256 thr, THREE-stage cp.async pipeline
// (loads get 2 compute periods to land; smem 3x36.9KB, still 2 CTAs/SM).
// PITCH 72 fp16 (144B = 36 words; conflict-free LDSM).
// OUTF=0: fp32 C.  OUTF=1: fp16 C.
// ---------------------------------------------------------------------------
#define PITCH 72
#define BUFB  (128 * PITCH * 2)       // 18432 B
#define STAGEB (2 * BUFB)             // 36864 B
#define GEMM_SMEM (3 * STAGEB)        // 110592 B

template <int OUTF>
__global__ void __launch_bounds__(256, 2) mma_gemm(
    const __half* __restrict__ A, const __half* __restrict__ Bm,
    float* __restrict__ C, __half* __restrict__ Cf, int M, int N, int K)
{
    extern __shared__ __align__(16) uint8_t smem[];
    const uint32_t sbase = smem_to_u32(smem);
    const int tid = threadIdx.x, lane = tid & 31, wid = tid >> 5;
    const int wr = wid & 3, wc = wid >> 2;
    const int bm = blockIdx.y * 128, bn = blockIdx.x * 128;
    const int NK = K / 64;

    float acc[2][8][4];
#pragma unroll
    for (int i = 0; i < 2; i++)
#pragma unroll
        for (int j = 0; j < 8; j++)
#pragma unroll
            for (int r = 0; r < 4; r++) acc[i][j][r] = 0.f;

#define ISSUE(kt, stg) do {                                                    \
        uint32_t sb_ = sbase + (stg) * STAGEB;                                 \
        _Pragma("unroll")                                                      \
        for (int hf = 0; hf < 4; hf++) {                                       \
            int c = tid + hf * 256;                                            \
            int row = c >> 3, colc = (c & 7) * 8;                              \
            uint32_t doff = (uint32_t)(row * (PITCH * 2) + colc * 2);          \
            CP16(sb_ + doff, A + (size_t)(bm + row) * K + (kt) * 64 + colc);   \
            CP16(sb_ + BUFB + doff,                                            \
                 Bm + (size_t)(bn + row) * K + (kt) * 64 + colc);              \
        }                                                                      \
        CP_COMMIT();                                                           \
    } while (0)

    ISSUE(0, 0);
    ISSUE(1, 1);

    for (int kt = 0; kt < NK; kt++) {
        const int cur = kt % 3;
        if (kt + 2 < NK) {
            ISSUE(kt + 2, (kt + 2) % 3);
            asm volatile("cp.async.wait_group 2;");
        } else if (kt + 1 < NK) {
            asm volatile("cp.async.wait_group 1;");
        } else {
            asm volatile("cp.async.wait_group 0;");
        }
        __syncthreads();

        const uint32_t sA = sbase + cur * STAGEB;
        const uint32_t sB = sA + BUFB;

#pragma unroll
        for (int ks = 0; ks < 4; ks++) {
            uint32_t ah[2][4];
#pragma unroll
            for (int i = 0; i < 2; i++) {
                uint32_t ra = (uint32_t)((wr * 32 + i * 16 + (lane & 15)) * (PITCH * 2)
                              + (ks * 16 + ((lane >> 4) << 3)) * 2);
                LDSM4(ah[i], sA + ra);
            }
#pragma unroll
            for (int jp = 0; jp < 4; jp++) {
                uint32_t rowb = (uint32_t)(wc * 64 + jp * 16 + ((lane >> 4) << 3) + (lane & 7));
                uint32_t colb = (uint32_t)(ks * 16 + (((lane >> 3) & 1) << 3));
                uint32_t rb = rowb * (PITCH * 2) + colb * 2;
                uint32_t bh4[4];
                LDSM4(bh4, sB + rb);
                MMAF16(acc[0][jp * 2],     ah[0], bh4[0], bh4[1]);
                MMAF16(acc[1][jp * 2],     ah[1], bh4[0], bh4[1]);
                MMAF16(acc[0][jp * 2 + 1], ah[0], bh4[2], bh4[3]);
                MMAF16(acc[1][jp * 2 + 1], ah[1], bh4[2], bh4[3]);
            }
        }
        __syncthreads();
    }

#pragma unroll
    for (int i = 0; i < 2; i++) {
        int mrow = bm + wr * 32 + i * 16 + (lane >> 2);
#pragma unroll
        for (int j = 0; j < 8; j++) {
            int ncol = bn + wc * 64 + j * 8 + (lane & 3) * 2;
            if (OUTF == 0) {
                *(float2*)(C + (size_t)mrow * N + ncol) =
                    make_float2(acc[i][j][0], acc[i][j][1]);
                *(float2*)(C + (size_t)(mrow + 8) * N + ncol) =
                    make_float2(acc[i][j][2], acc[i][j][3]);
            } else {
                *(__half2*)(Cf + (size_t)mrow * N + ncol) =
                    __floats2half2_rn(acc[i][j][0], acc[i][j][1]);
                *(__half2*)(Cf + (size_t)(mrow + 8) * N + ncol) =
                    __floats2half2_rn(acc[i][j][2], acc[i][j][3]);
            }
        }
    }
#undef ISSUE
}

// ---------------------------------------------------------------------------
// Lambda scalar
// ---------------------------------------------------------------------------
__global__ void lambda_kernel(const float* __restrict__ lq1, const float* __restrict__ lq2,
                              const float* __restrict__ lk1, const float* __restrict__ lk2)
{
    if (threadIdx.x == 0) {
        float d1 = 0.f, d2 = 0.f;
        for (int i = 0; i < HD_; i++) { d1 += lq1[i] * lk1[i]; d2 += lq2[i] * lk2[i]; }
        g_lam = expf(d1) - expf(d2) + 0.8f;
    }
}

// ---------------------------------------------------------------------------
// Tensor-core flash attention, single-pass fp16 (proven R10 version).
// Key tile = 128 keys per stage (two 64-key sub-tiles), one sync pair/tile.
// smem: Q[0,10240) | K stages 10240+stg*10240 (sub +5120)
//       | Vt stages 30720+stg*16384 (sub +8192)
// ---------------------------------------------------------------------------
#define SQ_OFF 0
#define SK_OFF 10240
#define SV_OFF 30720
#define ATT_SMEM 63488
#define NT_ (S_ / 128)

__global__ void __launch_bounds__(256, 2) attn_mma(
    const __half* __restrict__ q16, const __half* __restrict__ vt16,
    float* __restrict__ O1, float* __restrict__ O2)
{
    extern __shared__ __align__(16) uint8_t smem[];
    const uint32_t sbase = smem_to_u32(smem);
    const int tid = threadIdx.x, lane = tid & 31, wr = tid >> 5;
    const int bh = blockIdx.y, b = bh >> 4, h = bh & 15;
    const int half = blockIdx.z, d0 = half << 5;
    const int q0 = blockIdx.x * 128;

    const size_t qkoff = (size_t)b * S_ * QKV_N + h * HD_ + d0;

#pragma unroll
    for (int rep = 0; rep < 2; rep++) {
        int idx = tid + rep * 256;
        int row = idx >> 2, ch = idx & 3;
        size_t g = qkoff + (size_t)(q0 + row) * QKV_N + ch * 8;
        CP16(sbase + SQ_OFF + (uint32_t)(row * 80 + ch * 16), q16 + g);
    }

    // 128-key tile = two 64-key halves, one commit
    auto issue_tile = [&](int t, int stg) {
        uint32_t kb = sbase + SK_OFF + stg * 10240;
        uint32_t vb = sbase + SV_OFF + stg * 16384;
#pragma unroll
        for (int sub = 0; sub < 2; sub++) {
            {
                int row = tid >> 2, ch = tid & 3;
                size_t g = qkoff + (size_t)E_
                         + (size_t)(t * 128 + sub * 64 + row) * QKV_N + ch * 8;
                CP16(kb + sub * 5120 + (uint32_t)(row * 80 + ch * 16), q16 + g);
            }
#pragma unroll
            for (int rep = 0; rep < 2; rep++) {
                int idx = tid + rep * 256;
                int vrow = idx >> 3, vch = idx & 7;
                size_t g = (size_t)(bh * HD_ + vrow) * S_ + t * 128 + sub * 64 + vch * 8;
                CP16(vb + sub * 8192
                     + SMEM_SWIZZLE_128B((uint32_t)(vrow * 128 + vch * 16)), vt16 + g);
            }
        }
        CP_COMMIT();
    };

    issue_tile(0, 0);
    issue_tile(1, 1);

    float o[8][4];
#pragma unroll
    for (int j = 0; j < 8; j++)
#pragma unroll
        for (int r = 0; r < 4; r++) o[j][r] = 0.f;
    float m0 = -1e30f, m1 = -1e30f, l0 = 0.f, l1 = 0.f;
    uint32_t ah[2][4];

    const float CSC = 0.125f * 1.4426950408889634f;

    for (int t = 0; t < NT_; t++) {
        if (t < NT_ - 1) asm volatile("cp.async.wait_group 1;");
        else             asm volatile("cp.async.wait_group 0;");
        __syncthreads();

        if (t == 0) {
#pragma unroll
            for (int ks = 0; ks < 2; ks++) {
                uint32_t ra = sbase + SQ_OFF + (uint32_t)((wr * 16 + (lane & 15)) * 80
                              + (ks * 16 + ((lane >> 4) << 3)) * 2);
                LDSM4(ah[ks], ra);
            }
        }

#pragma unroll
        for (int sub = 0; sub < 2; sub++) {
            // ---- S = Q K^T (fp16) ----
            float s[8][4];
#pragma unroll
            for (int j = 0; j < 8; j++)
#pragma unroll
                for (int r = 0; r < 4; r++) s[j][r] = 0.f;

            const uint32_t kb = sbase + SK_OFF + (t & 1) * 10240 + sub * 5120;
#pragma unroll
            for (int ks = 0; ks < 2; ks++) {
#pragma unroll
                for (int jp = 0; jp < 4; jp++) {
                    uint32_t ra = kb + (uint32_t)(
                        (jp * 16 + ((lane >> 4) << 3) + (lane & 7)) * 80
                        + (ks * 16 + (((lane >> 3) & 1) << 3)) * 2);
                    uint32_t kh4[4];
                    LDSM4(kh4, ra);
                    MMAF16(s[jp * 2],     ah[ks], kh4[0], kh4[1]);
                    MMAF16(s[jp * 2 + 1], ah[ks], kh4[2], kh4[3]);
                }
            }

            // ---- online softmax ----
            float mx0 = -1e30f, mx1 = -1e30f;
#pragma unroll
            for (int j = 0; j < 8; j++) {
                mx0 = fmaxf(mx0, fmaxf(s[j][0], s[j][1]));
                mx1 = fmaxf(mx1, fmaxf(s[j][2], s[j][3]));
            }
            mx0 = fmaxf(mx0, __shfl_xor_sync(0xffffffffu, mx0, 1));
            mx0 = fmaxf(mx0, __shfl_xor_sync(0xffffffffu, mx0, 2));
            mx1 = fmaxf(mx1, __shfl_xor_sync(0xffffffffu, mx1, 1));
            mx1 = fmaxf(mx1, __shfl_xor_sync(0xffffffffu, mx1, 2));
            const float nm0 = fmaxf(m0, mx0 * CSC), nm1 = fmaxf(m1, mx1 * CSC);
            const float sc0 = exp2f(m0 - nm0), sc1 = exp2f(m1 - nm1);
            m0 = nm0; m1 = nm1;
            l0 *= sc0; l1 *= sc1;
#pragma unroll
            for (int j = 0; j < 8; j++) {
                o[j][0] *= sc0; o[j][1] *= sc0; o[j][2] *= sc1; o[j][3] *= sc1;
            }

            uint32_t pah[4][4];
#pragma unroll
            for (int kp = 0; kp < 4; kp++) {
#pragma unroll
                for (int fi = 0; fi < 2; fi++) {
                    const int jf = kp * 2 + fi;
                    float p0 = exp2f(fmaf(s[jf][0], CSC, -nm0));
                    float p1 = exp2f(fmaf(s[jf][1], CSC, -nm0));
                    float p2 = exp2f(fmaf(s[jf][2], CSC, -nm1));
                    float p3 = exp2f(fmaf(s[jf][3], CSC, -nm1));
                    l0 += p0 + p1; l1 += p2 + p3;
                    PACKH(pah[kp][fi * 2],     p0, p1);
                    PACKH(pah[kp][fi * 2 + 1], p2, p3);
                }
            }

            // ---- O += P V (fp16) ----
            const uint32_t vb = sbase + SV_OFF + (t & 1) * 16384 + sub * 8192;
#pragma unroll
            for (int kp = 0; kp < 4; kp++) {
#pragma unroll
                for (int jn = 0; jn < 4; jn++) {
                    uint32_t va = vb + SMEM_SWIZZLE_128B(
                        (uint32_t)((jn * 16 + ((lane >> 4) << 3) + (lane & 7)) * 128
                                   + (kp * 16 + (((lane >> 3) & 1) << 3)) * 2));
                    uint32_t vh4[4];
                    LDSM4(vh4, va);
                    MMAF16(o[jn * 2],     pah[kp], vh4[0], vh4[1]);
                    MMAF16(o[jn * 2 + 1], pah[kp], vh4[2], vh4[3]);
                }
            }
        }
        __syncthreads();
        if (t + 2 < NT_) issue_tile(t + 2, t & 1);
    }

    l0 += __shfl_xor_sync(0xffffffffu, l0, 1);
    l0 += __shfl_xor_sync(0xffffffffu, l0, 2);
    l1 += __shfl_xor_sync(0xffffffffu, l1, 1);
    l1 += __shfl_xor_sync(0xffffffffu, l1, 2);
    const float inv0 = 1.f / l0, inv1 = 1.f / l1;
    const int g = lane >> 2, tq = lane & 3;
    float* Op = (half ? O2 : O1) + ((size_t)bh * S_ + q0 + wr * 16) * HD_;
#pragma unroll
    for (int jf = 0; jf < 8; jf++) {
        int col = jf * 8 + tq * 2;
        *(float2*)(Op + (size_t)g * HD_ + col) =
            make_float2(o[jf][0] * inv0, o[jf][1] * inv0);
        *(float2*)(Op + (size_t)(g + 8) * HD_ + col) =
            make_float2(o[jf][2] * inv1, o[jf][3] * inv1);
    }
}

// ---------------------------------------------------------------------------
// Combine + RMSNorm + scrambled reshape -> fp16 (SMEM-transposed)
// ---------------------------------------------------------------------------
__global__ __launch_bounds__(256) void combine_kernel(
    const float* __restrict__ O1, const float* __restrict__ O2,
    const float* __restrict__ normw, __half* __restrict__ X2)
{
    __shared__ ushort smh[64][40];

    const int bh = blockIdx.y, b = bh >> 4, h = bh & 15;
    const int s0 = blockIdx.x * 32;
    const int tid = threadIdx.x;
    const int sr = tid >> 3;
    const int dp = (tid & 7) * 8;

    const float lam = g_lam;
    const size_t rbase = ((size_t)bh * S_ + s0 + sr) * HD_ + dp;

    float a[8];
    float ss = 0.f;
#pragma unroll
    for (int c = 0; c < 2; c++) {
        float4 v1 = *(const float4*)(O1 + rbase + c * 4);
        float4 v2 = *(const float4*)(O2 + rbase + c * 4);
        a[c * 4 + 0] = v1.x - lam * v2.x;
        a[c * 4 + 1] = v1.y - lam * v2.y;
        a[c * 4 + 2] = v1.z - lam * v2.z;
        a[c * 4 + 3] = v1.w - lam * v2.w;
#pragma unroll
        for (int j = 0; j < 4; j++) ss += a[c * 4 + j] * a[c * 4 + j];
    }
    ss += __shfl_xor_sync(0xffffffffu, ss, 1);
    ss += __shfl_xor_sync(0xffffffffu, ss, 2);
    ss += __shfl_xor_sync(0xffffffffu, ss, 4);
    const float inv = rsqrtf(ss * (1.f / 64.f) + 1e-6f) * (1.0f - 0.8f);

#pragma unroll
    for (int j = 0; j < 8; j++) {
        float v = a[j] * inv * normw[h * HD_ + dp + j];
        smh[dp + j][sr] = __half_as_ushort(__float2half(v));
    }
    __syncthreads();

    const int dr = tid >> 2, chunk = tid & 3;
    const int shi = s0 >> 10, slo0 = s0 & 1023;
    const size_t obase = (size_t)b * S_ * E_ + (size_t)(dr * 32 + h * 2 + shi) * E_
                       + slo0 + chunk * 8;
    *(uint4*)(X2 + obase) = *(const uint4*)(&smh[dr][chunk * 8]);
}

// ---------------------------------------------------------------------------
// Launch
// ---------------------------------------------------------------------------
extern "C" void kernel_launch(void* const* d_in, const int* in_sizes, int n_in,
                              void* d_out, int out_size)
{
    const float* x     = (const float*)d_in[0];
    const float* w_qkv = (const float*)d_in[1];
    const float* wo    = (const float*)d_in[2];
    const float* lq1   = (const float*)d_in[3];
    const float* lq2   = (const float*)d_in[4];
    const float* lk1   = (const float*)d_in[5];
    const float* lk2   = (const float*)d_in[6];
    const float* normw = (const float*)d_in[7];
    float* out = (float*)d_out;

    float *p_O1, *p_O2;
    cudaGetSymbolAddress((void**)&p_O1, g_O1);
    cudaGetSymbolAddress((void**)&p_O2, g_O2);
    __half *p_x16, *p_q16, *p_vt16, *p_X216, *p_wq16, *p_wo16;
    cudaGetSymbolAddress((void**)&p_x16, g_x16);
    cudaGetSymbolAddress((void**)&p_q16, g_qkv16);
    cudaGetSymbolAddress((void**)&p_vt16, g_vt16);
    cudaGetSymbolAddress((void**)&p_X216, g_X216);
    cudaGetSymbolAddress((void**)&p_wq16, g_wqkvT16);
    cudaGetSymbolAddress((void**)&p_wo16, g_woT16);

    cudaFuncSetAttribute(mma_gemm<0>, cudaFuncAttributeMaxDynamicSharedMemorySize, GEMM_SMEM);
    cudaFuncSetAttribute(mma_gemm<1>, cudaFuncAttributeMaxDynamicSharedMemorySize, GEMM_SMEM);
    cudaFuncSetAttribute(attn_mma, cudaFuncAttributeMaxDynamicSharedMemorySize, ATT_SMEM);

    // 0) fp16 conversions
    tof16_kernel<<<(M_TOK * E_) / (256 * 4), 256>>>(x, p_x16);
    transpose_f16<<<dim3(QKV_N / 32, E_ / 32), 256>>>(w_qkv, p_wq16, E_, QKV_N);
    transpose_f16<<<dim3(E_ / 32, E_ / 32), 256>>>(wo, p_wo16, E_, E_);

    // 1) QKV projection (fp16 single-pass, 3-stage pipeline) -> fp16
    mma_gemm<1><<<dim3(QKV_N / 128, M_TOK / 128), 256, GEMM_SMEM>>>(
        p_x16, p_wq16, nullptr, p_q16, M_TOK, QKV_N, E_);

    // 2) V transpose + lambda
    vtrans_kernel<<<dim3(S_ / 32, HD_ / 32, B_ * H_), 256>>>(p_q16, p_vt16);
    lambda_kernel<<<1, 32>>>(lq1, lq2, lk1, lk2);

    // 3) fp16 tensor-core attention, both halves
    attn_mma<<<dim3(S_ / 128, B_ * H_, 2), 256, ATT_SMEM>>>(
        p_q16, p_vt16, p_O1, p_O2);

    // 4) combine + RMSNorm + scrambled reshape -> fp16
    combine_kernel<<<dim3(S_ / 32, B_ * H_), 256>>>(p_O1, p_O2, normw, p_X216);

    // 5) output projection (fp16 single-pass, 3-stage pipeline) -> fp32 d_out
    mma_gemm<0><<<dim3(E_ / 128, M_TOK / 128), 256, GEMM_SMEM>>>(
        p_X216, p_wo16, out, nullptr, M_TOK, E_, E_);
}